// round 1
// baseline (speedup 1.0000x reference)
#include <cuda_runtime.h>
#include <math.h>
#include <float.h>

// Problem constants: B=64, S=512, D=128, K=1024; N = B*S
#define N_TOK 32768
#define DIM   128
#define KCODE 1024
#define BM    64
#define BN    64
#define ES_LD (DIM + 4)   // padded e-tile stride to break bank conflicts

// Scratch (no allocations allowed)
__device__ int    g_idx[N_TOK];
__device__ float  g_enorm[KCODE];
__device__ int    g_counts[KCODE];
__device__ int    g_valid;
__device__ double g_losssum;

// ---------------------------------------------------------------- init
__global__ void init_kernel() {
    int i = blockIdx.x * blockDim.x + threadIdx.x;
    if (i < KCODE) g_counts[i] = 0;
    if (i == 0) { g_valid = 0; g_losssum = 0.0; }
}

// ---------------------------------------------------------------- ||e||^2
// Sequential fp32 mul-then-add (NOT fma) to mirror jnp.sum(emb*emb, axis=1).
__global__ void enorm_kernel(const float* __restrict__ emb) {
    int k = blockIdx.x * blockDim.x + threadIdx.x;
    if (k >= KCODE) return;
    const float* e = emb + (size_t)k * DIM;
    float s = 0.f;
    for (int d = 0; d < DIM; d++) {
        float v = e[d];
        s = __fadd_rn(s, __fmul_rn(v, v));
    }
    g_enorm[k] = s;
}

// ---------------------------------------------------------------- argmin GEMM
// 256 threads; block computes BM=64 z-rows vs all K codes in BN=64 chunks.
// Thread (tx in [0,16), ty in [0,16)) owns a 4x4 (row x code) dot-product tile.
extern __shared__ float smem[];

__global__ __launch_bounds__(256) void argmin_kernel(const float* __restrict__ z,
                                                     const float* __restrict__ emb) {
    float* zs = smem;                 // [BM][DIM]     (reads are warp-broadcast)
    float* es = smem + BM * DIM;      // [BN][ES_LD]   (padded)
    const int tid = threadIdx.x;
    const int tx = tid & 15, ty = tid >> 4;
    const int row0 = blockIdx.x * BM;

    // Load z tile: straight float4 copy, coalesced, conflict-free.
    {
        const float4* zg = (const float4*)(z + (size_t)row0 * DIM);
        float4* zs4 = (float4*)zs;
        #pragma unroll
        for (int i = 0; i < (BM * DIM / 4) / 256; i++)
            zs4[tid + i * 256] = zg[tid + i * 256];
    }
    __syncthreads();

    // ||z||^2 for my 4 rows — sequential fp32 mul-then-add (reference rounding).
    float zn[4];
    #pragma unroll
    for (int i = 0; i < 4; i++) {
        const float* zr = zs + (4 * ty + i) * DIM;
        float s = 0.f;
        for (int d = 0; d < DIM; d++) {
            float v = zr[d];
            s = __fadd_rn(s, __fmul_rn(v, v));
        }
        zn[i] = s;
    }

    float minv[4]; int mini[4];
    #pragma unroll
    for (int i = 0; i < 4; i++) { minv[i] = FLT_MAX; mini[i] = 0; }

    for (int c0 = 0; c0 < KCODE; c0 += BN) {
        __syncthreads();   // protect previous chunk's es reads
        // Load e chunk into padded smem; conflict-free stores.
        #pragma unroll
        for (int i = 0; i < (BN * DIM / 4) / 256; i++) {
            int f  = tid + i * 256;
            int c  = f >> 5;             // DIM/4 = 32 float4 per row
            int dp = (f & 31) << 2;
            float4 v = *(const float4*)(emb + (size_t)(c0 + c) * DIM + dp);
            *(float4*)(es + c * ES_LD + dp) = v;
        }
        __syncthreads();

        float acc[4][4];
        #pragma unroll
        for (int i = 0; i < 4; i++)
            #pragma unroll
            for (int j = 0; j < 4; j++) acc[i][j] = 0.f;

        #pragma unroll 2
        for (int d = 0; d < DIM; d += 4) {
            float4 za[4], eb[4];
            #pragma unroll
            for (int i = 0; i < 4; i++)
                za[i] = *(const float4*)(zs + (4 * ty + i) * DIM + d);
            #pragma unroll
            for (int j = 0; j < 4; j++)
                eb[j] = *(const float4*)(es + (4 * tx + j) * ES_LD + d);
            #pragma unroll
            for (int i = 0; i < 4; i++)
                #pragma unroll
                for (int j = 0; j < 4; j++) {
                    acc[i][j] = fmaf(za[i].x, eb[j].x, acc[i][j]);
                    acc[i][j] = fmaf(za[i].y, eb[j].y, acc[i][j]);
                    acc[i][j] = fmaf(za[i].z, eb[j].z, acc[i][j]);
                    acc[i][j] = fmaf(za[i].w, eb[j].w, acc[i][j]);
                }
        }

        // dist = (znorm + enorm) - 2*dot, rounded exactly like the reference.
        #pragma unroll
        for (int j = 0; j < 4; j++) {
            int code = c0 + 4 * tx + j;
            float en = g_enorm[code];
            #pragma unroll
            for (int i = 0; i < 4; i++) {
                float q = __fadd_rn(__fadd_rn(zn[i], en), -2.0f * acc[i][j]);
                if (q < minv[i]) { minv[i] = q; mini[i] = code; }  // first-index ties kept
            }
        }
    }

    // Cross-thread argmin (16 tx lanes per row), first-index tie-break.
    __syncthreads();
    float* rv = smem;                       // [BM][16]
    int*   ri = (int*)(smem + BM * 16);     // [BM][16]
    #pragma unroll
    for (int i = 0; i < 4; i++) {
        rv[(4 * ty + i) * 16 + tx] = minv[i];
        ri[(4 * ty + i) * 16 + tx] = mini[i];
    }
    __syncthreads();
    if (tid < BM) {
        float bv = rv[tid * 16]; int bi = ri[tid * 16];
        #pragma unroll
        for (int t = 1; t < 16; t++) {
            float v = rv[tid * 16 + t]; int ix = ri[tid * 16 + t];
            if (v < bv || (v == bv && ix < bi)) { bv = v; bi = ix; }
        }
        g_idx[row0 + tid] = bi;
    }
}

// ---------------------------------------------------------------- gather + loss + hist
// One warp per row; straight-through output replicates z + (z_q - z) rounding.
__global__ void quantize_kernel(const float* __restrict__ z,
                                const float* __restrict__ emb,
                                const unsigned char* __restrict__ mask,
                                float* __restrict__ out) {
    const int warp = threadIdx.x >> 5;
    const int lane = threadIdx.x & 31;
    const int row  = blockIdx.x * 8 + warp;
    const int code = g_idx[row];

    const float4 zv = *(const float4*)(z   + (size_t)row  * DIM + lane * 4);
    const float4 ev = *(const float4*)(emb + (size_t)code * DIM + lane * 4);

    float dx = __fadd_rn(ev.x, -zv.x);
    float dy = __fadd_rn(ev.y, -zv.y);
    float dz = __fadd_rn(ev.z, -zv.z);
    float dw = __fadd_rn(ev.w, -zv.w);

    float4 o;
    o.x = __fadd_rn(zv.x, dx);
    o.y = __fadd_rn(zv.y, dy);
    o.z = __fadd_rn(zv.z, dz);
    o.w = __fadd_rn(zv.w, dw);
    *(float4*)(out + (size_t)row * DIM + lane * 4) = o;

    float ss = dx * dx + dy * dy + dz * dz + dw * dw;
    #pragma unroll
    for (int off = 16; off; off >>= 1) ss += __shfl_xor_sync(0xffffffffu, ss, off);

    __shared__ float sps[8];
    if (lane == 0) {
        sps[warp] = ss;
        int v = mask[row] ? 0 : 1;
        atomicAdd(&g_valid, v);
        if (v) atomicAdd(&g_counts[code], 1);
    }
    __syncthreads();
    if (threadIdx.x == 0) {
        float b = 0.f;
        #pragma unroll
        for (int w = 0; w < 8; w++) b += sps[w];
        atomicAdd(&g_losssum, (double)b);
    }
}

// ---------------------------------------------------------------- scalars
__global__ void finalize_kernel(float* __restrict__ out, long long out_size) {
    __shared__ float red[1024];
    const int k = threadIdx.x;
    float valid = (float)g_valid;
    float p = __fdiv_rn((float)g_counts[k], valid);
    red[k] = __fmul_rn(p, logf(__fadd_rn(p, 1e-10f)));
    __syncthreads();
    for (int s = 512; s > 0; s >>= 1) {
        if (k < s) red[k] += red[k + s];
        __syncthreads();
    }
    if (k == 0 && out_size >= (long long)N_TOK * DIM + 2) {
        double mean = g_losssum / (double)((long long)N_TOK * DIM);
        float v = (float)mean;                     // q_latent == e_latent in forward value
        out[(long long)N_TOK * DIM]     = __fadd_rn(v, __fmul_rn(0.25f, v));
        out[(long long)N_TOK * DIM + 1] = expf(-red[0]);
    }
}

// ---------------------------------------------------------------- launch
extern "C" void kernel_launch(void* const* d_in, const int* in_sizes, int n_in,
                              void* d_out, int out_size) {
    const float* z = nullptr;
    const float* emb = nullptr;
    const unsigned char* mask = nullptr;
    for (int i = 0; i < n_in; i++) {
        if      (in_sizes[i] == N_TOK * DIM) z    = (const float*)d_in[i];
        else if (in_sizes[i] == KCODE * DIM) emb  = (const float*)d_in[i];
        else if (in_sizes[i] == N_TOK)       mask = (const unsigned char*)d_in[i];
    }
    float* out = (float*)d_out;

    const size_t smem_bytes = (size_t)(BM * DIM + BN * ES_LD) * sizeof(float);
    cudaFuncSetAttribute(argmin_kernel, cudaFuncAttributeMaxDynamicSharedMemorySize,
                         (int)smem_bytes);

    init_kernel   <<<4, 256>>>();
    enorm_kernel  <<<4, 256>>>(emb);
    argmin_kernel <<<N_TOK / BM, 256, smem_bytes>>>(z, emb);
    quantize_kernel<<<N_TOK / 8, 256>>>(z, emb, mask, out);
    finalize_kernel<<<1, 1024>>>(out, (long long)out_size);
}

// round 2
// speedup vs baseline: 2.4042x; 2.4042x over previous
#include <cuda_runtime.h>
#include <math.h>
#include <float.h>

// Problem constants: B=64, S=512, D=128, K=1024; N = B*S
#define N_TOK 32768
#define DIM   128
#define KCODE 1024
#define BM    64
#define BN    128
#define ES_LD (DIM + 4)   // e-tile row stride: 4*ES_LD % 32 == 16, but lanes are
                          // stride-1 rows now (see code map), 132 % 32 = 4 -> floor

// Scratch (no allocations allowed)
__device__ int    g_idx[N_TOK];
__device__ float  g_enorm[KCODE];
__device__ int    g_counts[KCODE];
__device__ int    g_valid;
__device__ double g_losssum;

// packed f32x2 fma: d.lo += a.lo*b.lo ; d.hi += a.hi*b.hi
__device__ __forceinline__ void fma2(unsigned long long& acc,
                                     unsigned long long a,
                                     unsigned long long b) {
    asm("fma.rn.f32x2 %0, %1, %2, %0;" : "+l"(acc) : "l"(a), "l"(b));
}

// ---------------------------------------------------------------- init
__global__ void init_kernel() {
    int i = blockIdx.x * blockDim.x + threadIdx.x;
    if (i < KCODE) g_counts[i] = 0;
    if (i == 0) { g_valid = 0; g_losssum = 0.0; }
}

// ---------------------------------------------------------------- ||e||^2
// Sequential fp32 mul-then-add (NOT fma) to mirror jnp.sum(emb*emb, axis=1).
__global__ void enorm_kernel(const float* __restrict__ emb) {
    int k = blockIdx.x * blockDim.x + threadIdx.x;
    if (k >= KCODE) return;
    const float* e = emb + (size_t)k * DIM;
    float s = 0.f;
    for (int d = 0; d < DIM; d++) {
        float v = e[d];
        s = __fadd_rn(s, __fmul_rn(v, v));
    }
    g_enorm[k] = s;
}

// ---------------------------------------------------------------- argmin GEMM
// 256 threads. Block tile: BM=64 z-rows x BN=128 codes per chunk (8 chunks).
// Thread (tx in [0,16), ty in [0,16)): rows {4ty+i}, codes {tx + 16p, p<8}.
// Packed-f32x2 accumulators: lo lane = even-d partial, hi lane = odd-d partial.
extern __shared__ float smem[];

__global__ __launch_bounds__(256, 2) void argmin_kernel(const float* __restrict__ z,
                                                        const float* __restrict__ emb) {
    float* zs = smem;                 // [BM][DIM]
    float* es = smem + BM * DIM;      // [BN][ES_LD]
    const int tid = threadIdx.x;
    const int tx = tid & 15, ty = tid >> 4;
    const int row0 = blockIdx.x * BM;

    // Load z tile: coalesced float4 copy.
    {
        const float4* zg = (const float4*)(z + (size_t)row0 * DIM);
        float4* zs4 = (float4*)zs;
        #pragma unroll
        for (int i = 0; i < (BM * DIM / 4) / 256; i++)
            zs4[tid + i * 256] = zg[tid + i * 256];
    }
    __syncthreads();

    // ||z||^2 for my 4 rows — sequential fp32 mul-then-add (reference rounding).
    float zn[4];
    #pragma unroll
    for (int i = 0; i < 4; i++) {
        const float* zr = zs + (4 * ty + i) * DIM;
        float s = 0.f;
        for (int d = 0; d < DIM; d++) {
            float v = zr[d];
            s = __fadd_rn(s, __fmul_rn(v, v));
        }
        zn[i] = s;
    }

    float minv[4]; int mini[4];
    #pragma unroll
    for (int i = 0; i < 4; i++) { minv[i] = FLT_MAX; mini[i] = 0; }

    for (int c0 = 0; c0 < KCODE; c0 += BN) {
        __syncthreads();   // protect previous chunk's es reads
        // Load e chunk [BN][DIM] into padded smem. Coalesced gmem, conflict-free smem.
        #pragma unroll
        for (int i = 0; i < (BN * DIM / 4) / 256; i++) {
            int f  = tid + i * 256;
            int c  = f >> 5;             // DIM/4 = 32 float4 per row
            int dp = (f & 31) << 2;
            float4 v = *(const float4*)(emb + (size_t)(c0 + c) * DIM + dp);
            *(float4*)(es + c * ES_LD + dp) = v;
        }
        __syncthreads();

        unsigned long long acc[4][8];
        #pragma unroll
        for (int i = 0; i < 4; i++)
            #pragma unroll
            for (int j = 0; j < 8; j++) acc[i][j] = 0ull;

        #pragma unroll 4
        for (int d = 0; d < DIM; d += 4) {
            // za[i] = (z[r][d],z[r][d+1]) , (z[r][d+2],z[r][d+3]) as two u64 pairs
            ulonglong2 za[4];
            #pragma unroll
            for (int i = 0; i < 4; i++)
                za[i] = *(const ulonglong2*)(zs + (4 * ty + i) * DIM + d);
            #pragma unroll
            for (int j = 0; j < 8; j++) {
                ulonglong2 eb = *(const ulonglong2*)(es + (tx + 16 * j) * ES_LD + d);
                #pragma unroll
                for (int i = 0; i < 4; i++) {
                    fma2(acc[i][j], za[i].x, eb.x);
                    fma2(acc[i][j], za[i].y, eb.y);
                }
            }
        }

        // dist = (znorm + enorm) - 2*dot, same rounding pattern as before.
        #pragma unroll
        for (int j = 0; j < 8; j++) {
            int code = c0 + tx + 16 * j;
            float en = g_enorm[code];
            #pragma unroll
            for (int i = 0; i < 4; i++) {
                float2 p = *(float2*)&acc[i][j];
                float dot = __fadd_rn(p.x, p.y);
                float q = __fadd_rn(__fadd_rn(zn[i], en), -2.0f * dot);
                if (q < minv[i]) { minv[i] = q; mini[i] = code; }
            }
        }
    }

    // Cross-thread argmin (16 tx lanes per row), first-index tie-break.
    __syncthreads();
    float* rv = smem;                       // [BM][16]
    int*   ri = (int*)(smem + BM * 16);     // [BM][16]
    #pragma unroll
    for (int i = 0; i < 4; i++) {
        rv[(4 * ty + i) * 16 + tx] = minv[i];
        ri[(4 * ty + i) * 16 + tx] = mini[i];
    }
    __syncthreads();
    if (tid < BM) {
        float bv = rv[tid * 16]; int bi = ri[tid * 16];
        #pragma unroll
        for (int t = 1; t < 16; t++) {
            float v = rv[tid * 16 + t]; int ix = ri[tid * 16 + t];
            if (v < bv || (v == bv && ix < bi)) { bv = v; bi = ix; }
        }
        g_idx[row0 + tid] = bi;
    }
}

// ---------------------------------------------------------------- gather + loss + hist
__global__ void quantize_kernel(const float* __restrict__ z,
                                const float* __restrict__ emb,
                                const unsigned char* __restrict__ mask,
                                float* __restrict__ out) {
    const int warp = threadIdx.x >> 5;
    const int lane = threadIdx.x & 31;
    const int row  = blockIdx.x * 8 + warp;
    const int code = g_idx[row];

    const float4 zv = *(const float4*)(z   + (size_t)row  * DIM + lane * 4);
    const float4 ev = *(const float4*)(emb + (size_t)code * DIM + lane * 4);

    float dx = __fadd_rn(ev.x, -zv.x);
    float dy = __fadd_rn(ev.y, -zv.y);
    float dz = __fadd_rn(ev.z, -zv.z);
    float dw = __fadd_rn(ev.w, -zv.w);

    float4 o;
    o.x = __fadd_rn(zv.x, dx);
    o.y = __fadd_rn(zv.y, dy);
    o.z = __fadd_rn(zv.z, dz);
    o.w = __fadd_rn(zv.w, dw);
    *(float4*)(out + (size_t)row * DIM + lane * 4) = o;

    float ss = dx * dx + dy * dy + dz * dz + dw * dw;
    #pragma unroll
    for (int off = 16; off; off >>= 1) ss += __shfl_xor_sync(0xffffffffu, ss, off);

    __shared__ float sps[8];
    if (lane == 0) {
        sps[warp] = ss;
        int v = mask[row] ? 0 : 1;
        atomicAdd(&g_valid, v);
        if (v) atomicAdd(&g_counts[code], 1);
    }
    __syncthreads();
    if (threadIdx.x == 0) {
        float b = 0.f;
        #pragma unroll
        for (int w = 0; w < 8; w++) b += sps[w];
        atomicAdd(&g_losssum, (double)b);
    }
}

// ---------------------------------------------------------------- scalars
__global__ void finalize_kernel(float* __restrict__ out, long long out_size) {
    __shared__ float red[1024];
    const int k = threadIdx.x;
    float valid = (float)g_valid;
    float p = __fdiv_rn((float)g_counts[k], valid);
    red[k] = __fmul_rn(p, logf(__fadd_rn(p, 1e-10f)));
    __syncthreads();
    for (int s = 512; s > 0; s >>= 1) {
        if (k < s) red[k] += red[k + s];
        __syncthreads();
    }
    if (k == 0 && out_size >= (long long)N_TOK * DIM + 2) {
        double mean = g_losssum / (double)((long long)N_TOK * DIM);
        float v = (float)mean;
        out[(long long)N_TOK * DIM]     = __fadd_rn(v, __fmul_rn(0.25f, v));
        out[(long long)N_TOK * DIM + 1] = expf(-red[0]);
    }
}

// ---------------------------------------------------------------- launch
extern "C" void kernel_launch(void* const* d_in, const int* in_sizes, int n_in,
                              void* d_out, int out_size) {
    const float* z = nullptr;
    const float* emb = nullptr;
    const unsigned char* mask = nullptr;
    for (int i = 0; i < n_in; i++) {
        if      (in_sizes[i] == N_TOK * DIM) z    = (const float*)d_in[i];
        else if (in_sizes[i] == KCODE * DIM) emb  = (const float*)d_in[i];
        else if (in_sizes[i] == N_TOK)       mask = (const unsigned char*)d_in[i];
    }
    float* out = (float*)d_out;

    const size_t smem_bytes = (size_t)(BM * DIM + BN * ES_LD) * sizeof(float);
    cudaFuncSetAttribute(argmin_kernel, cudaFuncAttributeMaxDynamicSharedMemorySize,
                         (int)smem_bytes);

    init_kernel   <<<4, 256>>>();
    enorm_kernel  <<<4, 256>>>(emb);
    argmin_kernel <<<N_TOK / BM, 256, smem_bytes>>>(z, emb);
    quantize_kernel<<<N_TOK / 8, 256>>>(z, emb, mask, out);
    finalize_kernel<<<1, 1024>>>(out, (long long)out_size);
}

// round 3
// speedup vs baseline: 2.5259x; 1.0506x over previous
#include <cuda_runtime.h>
#include <math.h>
#include <float.h>

// Problem constants: B=64, S=512, D=128, K=1024; N = B*S
#define N_TOK 32768
#define DIM   128
#define KCODE 1024
#define BM    64
#define BN    128
#define ES_LD (DIM + 4)   // 132: lane stride 132%32==4 banks -> eb LDS.128 at 2-phase floor
#define QBLK  8           // rows per quantize block
#define NQB   (N_TOK / QBLK)

// Scratch (no allocations allowed)
__device__ int    g_idx[N_TOK];
__device__ float  g_enorm[KCODE];
__device__ int    g_counts[KCODE];
__device__ double g_losspart[NQB];

// packed f32x2 fma: d.lo += a.lo*b.lo ; d.hi += a.hi*b.hi
__device__ __forceinline__ void fma2(unsigned long long& acc,
                                     unsigned long long a,
                                     unsigned long long b) {
    asm("fma.rn.f32x2 %0, %1, %2, %0;" : "+l"(acc) : "l"(a), "l"(b));
}

// ---------------------------------------------------------------- init
__global__ void init_kernel() {
    int i = blockIdx.x * blockDim.x + threadIdx.x;
    if (i < KCODE) g_counts[i] = 0;
}

// ---------------------------------------------------------------- ||e||^2
// Sequential fp32 mul-then-add (NOT fma) to mirror jnp.sum(emb*emb, axis=1).
__global__ void enorm_kernel(const float* __restrict__ emb) {
    int k = blockIdx.x * blockDim.x + threadIdx.x;
    if (k >= KCODE) return;
    const float* e = emb + (size_t)k * DIM;
    float s = 0.f;
    for (int d = 0; d < DIM; d++) {
        float v = e[d];
        s = __fadd_rn(s, __fmul_rn(v, v));
    }
    g_enorm[k] = s;
}

// ---------------------------------------------------------------- argmin GEMM
// 128 threads (tx in [0,16), ty in [0,8)). Thread tile: 8 rows x 8 codes.
// Block tile: BM=64 z-rows vs all K codes in BN=128 chunks (8 chunks).
// rows: 8*ty + i ; codes: tx + 16*j (same map as R2 -> bit-identical distances).
// Packed-f32x2 accumulators: lo lane = even-d partial, hi lane = odd-d partial.
extern __shared__ float smem[];

__global__ __launch_bounds__(128, 2) void argmin_kernel(const float* __restrict__ z,
                                                        const float* __restrict__ emb) {
    float* zs = smem;                 // [BM][DIM]
    float* es = smem + BM * DIM;      // [BN][ES_LD]
    const int tid = threadIdx.x;
    const int tx = tid & 15, ty = tid >> 4;
    const int row0 = blockIdx.x * BM;

    // Load z tile: coalesced float4 copy (2048 float4 / 128 threads = 16 iters).
    {
        const float4* zg = (const float4*)(z + (size_t)row0 * DIM);
        float4* zs4 = (float4*)zs;
        #pragma unroll
        for (int i = 0; i < (BM * DIM / 4) / 128; i++)
            zs4[tid + i * 128] = zg[tid + i * 128];
    }
    __syncthreads();

    // ||z||^2 for my 8 rows — sequential fp32 mul-then-add (reference rounding).
    float zn[8];
    #pragma unroll
    for (int i = 0; i < 8; i++) {
        const float* zr = zs + (8 * ty + i) * DIM;
        float s = 0.f;
        for (int d = 0; d < DIM; d++) {
            float v = zr[d];
            s = __fadd_rn(s, __fmul_rn(v, v));
        }
        zn[i] = s;
    }

    float minv[8]; int mini[8];
    #pragma unroll
    for (int i = 0; i < 8; i++) { minv[i] = FLT_MAX; mini[i] = 0; }

    for (int c0 = 0; c0 < KCODE; c0 += BN) {
        __syncthreads();   // protect previous chunk's es reads
        // Load e chunk [BN][DIM] into padded smem (4096 float4 / 128 thr = 32 iters).
        #pragma unroll
        for (int i = 0; i < (BN * DIM / 4) / 128; i++) {
            int f  = tid + i * 128;
            int c  = f >> 5;             // DIM/4 = 32 float4 per row
            int dp = (f & 31) << 2;
            float4 v = *(const float4*)(emb + (size_t)(c0 + c) * DIM + dp);
            *(float4*)(es + c * ES_LD + dp) = v;
        }
        __syncthreads();

        unsigned long long acc[8][8];
        #pragma unroll
        for (int i = 0; i < 8; i++)
            #pragma unroll
            for (int j = 0; j < 8; j++) acc[i][j] = 0ull;

        #pragma unroll 2
        for (int d = 0; d < DIM; d += 4) {
            ulonglong2 za[8];
            #pragma unroll
            for (int i = 0; i < 8; i++)
                za[i] = *(const ulonglong2*)(zs + (8 * ty + i) * DIM + d);
            #pragma unroll
            for (int j = 0; j < 8; j++) {
                ulonglong2 eb = *(const ulonglong2*)(es + (tx + 16 * j) * ES_LD + d);
                #pragma unroll
                for (int i = 0; i < 8; i++) {
                    fma2(acc[i][j], za[i].x, eb.x);
                    fma2(acc[i][j], za[i].y, eb.y);
                }
            }
        }

        // dist = (znorm + enorm) - 2*dot, same rounding pattern as before.
        #pragma unroll
        for (int j = 0; j < 8; j++) {
            int code = c0 + tx + 16 * j;
            float en = g_enorm[code];
            #pragma unroll
            for (int i = 0; i < 8; i++) {
                float2 p = *(float2*)&acc[i][j];
                float dot = __fadd_rn(p.x, p.y);
                float q = __fadd_rn(__fadd_rn(zn[i], en), -2.0f * dot);
                if (q < minv[i]) { minv[i] = q; mini[i] = code; }
            }
        }
    }

    // Cross-thread argmin (16 tx lanes per row), first-index tie-break.
    __syncthreads();
    float* rv = smem;                       // [BM][16]
    int*   ri = (int*)(smem + BM * 16);     // [BM][16]
    #pragma unroll
    for (int i = 0; i < 8; i++) {
        rv[(8 * ty + i) * 16 + tx] = minv[i];
        ri[(8 * ty + i) * 16 + tx] = mini[i];
    }
    __syncthreads();
    if (tid < BM) {
        float bv = rv[tid * 16]; int bi = ri[tid * 16];
        #pragma unroll
        for (int t = 1; t < 16; t++) {
            float v = rv[tid * 16 + t]; int ix = ri[tid * 16 + t];
            if (v < bv || (v == bv && ix < bi)) { bv = v; bi = ix; }
        }
        g_idx[row0 + tid] = bi;
    }
}

// ---------------------------------------------------------------- gather + loss + hist
// One warp per row. No contended atomics: loss partial stored per block,
// valid-count moved to finalize. Only spread histogram atomics remain.
__global__ void quantize_kernel(const float* __restrict__ z,
                                const float* __restrict__ emb,
                                const unsigned char* __restrict__ mask,
                                float* __restrict__ out) {
    const int warp = threadIdx.x >> 5;
    const int lane = threadIdx.x & 31;
    const int row  = blockIdx.x * QBLK + warp;
    const int code = g_idx[row];

    const float4 zv = *(const float4*)(z   + (size_t)row  * DIM + lane * 4);
    const float4 ev = *(const float4*)(emb + (size_t)code * DIM + lane * 4);

    float dx = __fadd_rn(ev.x, -zv.x);
    float dy = __fadd_rn(ev.y, -zv.y);
    float dz = __fadd_rn(ev.z, -zv.z);
    float dw = __fadd_rn(ev.w, -zv.w);

    float4 o;
    o.x = __fadd_rn(zv.x, dx);
    o.y = __fadd_rn(zv.y, dy);
    o.z = __fadd_rn(zv.z, dz);
    o.w = __fadd_rn(zv.w, dw);
    *(float4*)(out + (size_t)row * DIM + lane * 4) = o;

    float ss = dx * dx + dy * dy + dz * dz + dw * dw;
    #pragma unroll
    for (int off = 16; off; off >>= 1) ss += __shfl_xor_sync(0xffffffffu, ss, off);

    __shared__ float sps[QBLK];
    if (lane == 0) {
        sps[warp] = ss;
        if (!mask[row]) atomicAdd(&g_counts[code], 1);   // spread across 1024 addrs
    }
    __syncthreads();
    if (threadIdx.x == 0) {
        double b = 0.0;
        #pragma unroll
        for (int w = 0; w < QBLK; w++) b += (double)sps[w];
        g_losspart[blockIdx.x] = b;
    }
}

// ---------------------------------------------------------------- scalars
__global__ void finalize_kernel(const unsigned char* __restrict__ mask,
                                float* __restrict__ out, long long out_size) {
    __shared__ double dred[1024];
    __shared__ int    ired[1024];
    __shared__ float  fred[1024];
    const int k = threadIdx.x;

    // valid = N - sum(mask), loss partial reduce (both in one pass)
    int vsum = 0;
    {
        const uchar4* m4 = (const uchar4*)mask;
        #pragma unroll
        for (int i = 0; i < (N_TOK / 4) / 1024; i++) {
            uchar4 m = m4[k + i * 1024];
            vsum += (m.x ? 0 : 1) + (m.y ? 0 : 1) + (m.z ? 0 : 1) + (m.w ? 0 : 1);
        }
    }
    double lsum = 0.0;
    #pragma unroll
    for (int i = 0; i < NQB / 1024; i++) lsum += g_losspart[k + i * 1024];
    dred[k] = lsum;
    ired[k] = vsum;
    __syncthreads();
    for (int s = 512; s > 0; s >>= 1) {
        if (k < s) { dred[k] += dred[k + s]; ired[k] += ired[k + s]; }
        __syncthreads();
    }
    const float valid = (float)ired[0];
    const double losssum = dred[0];

    // perplexity
    float p = __fdiv_rn((float)g_counts[k], valid);
    fred[k] = __fmul_rn(p, logf(__fadd_rn(p, 1e-10f)));
    __syncthreads();
    for (int s = 512; s > 0; s >>= 1) {
        if (k < s) fred[k] += fred[k + s];
        __syncthreads();
    }
    if (k == 0 && out_size >= (long long)N_TOK * DIM + 2) {
        double mean = losssum / (double)((long long)N_TOK * DIM);
        float v = (float)mean;                 // q_latent == e_latent in forward value
        out[(long long)N_TOK * DIM]     = __fadd_rn(v, __fmul_rn(0.25f, v));
        out[(long long)N_TOK * DIM + 1] = expf(-fred[0]);
    }
}

// ---------------------------------------------------------------- launch
extern "C" void kernel_launch(void* const* d_in, const int* in_sizes, int n_in,
                              void* d_out, int out_size) {
    const float* z = nullptr;
    const float* emb = nullptr;
    const unsigned char* mask = nullptr;
    for (int i = 0; i < n_in; i++) {
        if      (in_sizes[i] == N_TOK * DIM) z    = (const float*)d_in[i];
        else if (in_sizes[i] == KCODE * DIM) emb  = (const float*)d_in[i];
        else if (in_sizes[i] == N_TOK)       mask = (const unsigned char*)d_in[i];
    }
    float* out = (float*)d_out;

    const size_t smem_bytes = (size_t)(BM * DIM + BN * ES_LD) * sizeof(float);
    cudaFuncSetAttribute(argmin_kernel, cudaFuncAttributeMaxDynamicSharedMemorySize,
                         (int)smem_bytes);

    init_kernel    <<<4, 256>>>();
    enorm_kernel   <<<4, 256>>>(emb);
    argmin_kernel  <<<N_TOK / BM, 128, smem_bytes>>>(z, emb);
    quantize_kernel<<<NQB, QBLK * 32>>>(z, emb, mask, out);
    finalize_kernel<<<1, 1024>>>(mask, out, (long long)out_size);
}

// round 5
// speedup vs baseline: 5.0869x; 2.0139x over previous
#include <cuda_runtime.h>
#include <cuda_fp16.h>
#include <math.h>
#include <float.h>
#include <stdint.h>

// Problem constants: B=64, S=512, D=128, K=1024; N = B*S
#define N_TOK 32768
#define DIM   128
#define KCODE 1024
#define QBLK  8
#define NQB   (N_TOK / QBLK)

#define BN        64          // codes per chunk
#define NCHUNK    (KCODE / BN)
#define EPAD      136         // halves per padded e-row (272 B; 68 words % 32 == 4)
#define CHUNK_B   (BN * EPAD * 2)        // 17408 bytes per split per chunk
#define CHUNK_U4  (CHUNK_B / 16)         // 1088 uint4
#define BUF_B     (2 * CHUNK_B)          // hi+lo = 34816
#define SMEM_B    (2 * BUF_B)            // double buffer = 69632

// Scratch (no allocations allowed)
__device__ int    g_idx[N_TOK];
__device__ float  g_enorm[KCODE];
__device__ int    g_counts[KCODE];
__device__ double g_losspart[NQB];
__device__ __half g_ehi[KCODE * EPAD];   // e * 1024, fp16 hi, padded rows
__device__ __half g_elo[KCODE * EPAD];   // residual lo

// ------------------------------------------------------------ helpers
__device__ __forceinline__ uint32_t smem_u32(const void* p) {
    uint32_t a;
    asm("{ .reg .u64 t; cvta.to.shared.u64 t, %1; cvt.u32.u64 %0, t; }" : "=r"(a) : "l"(p));
    return a;
}
__device__ __forceinline__ void cpasync16(uint32_t dst, const void* src) {
    asm volatile("{\n\t.reg .u64 gp;\n\tcvta.to.global.u64 gp, %1;\n\t"
                 "cp.async.cg.shared.global [%0], [gp], 16;\n\t}"
                 :: "r"(dst), "l"(src));
}
#define CP_COMMIT() asm volatile("cp.async.commit_group;" ::: "memory")
#define CP_WAIT0()  asm volatile("cp.async.wait_group 0;" ::: "memory")

// m16n8k16 row.col f32.f16.f16.f32
__device__ __forceinline__ void mma16816(float* c, const uint32_t* a,
                                         uint32_t b0, uint32_t b1) {
    asm volatile("mma.sync.aligned.m16n8k16.row.col.f32.f16.f16.f32 "
                 "{%0,%1,%2,%3}, {%4,%5,%6,%7}, {%8,%9}, {%0,%1,%2,%3};"
                 : "+f"(c[0]), "+f"(c[1]), "+f"(c[2]), "+f"(c[3])
                 : "r"(a[0]), "r"(a[1]), "r"(a[2]), "r"(a[3]), "r"(b0), "r"(b1));
}
__device__ __forceinline__ void split2(float2 v, uint32_t& h, uint32_t& l) {
    __half hx = __float2half_rn(v.x), hy = __float2half_rn(v.y);
    __half lx = __float2half_rn(v.x - __half2float(hx));
    __half ly = __float2half_rn(v.y - __half2float(hy));
    h = ((uint32_t)__half_as_ushort(hy) << 16) | __half_as_ushort(hx);
    l = ((uint32_t)__half_as_ushort(ly) << 16) | __half_as_ushort(lx);
}

// ---------------------------------------------------------------- init
__global__ void init_kernel() {
    int i = blockIdx.x * blockDim.x + threadIdx.x;
    if (i < KCODE) g_counts[i] = 0;
}

// ---------------------------------------------------------------- ||e||^2 (reference order)
__global__ void enorm_kernel(const float* __restrict__ emb) {
    int k = blockIdx.x * blockDim.x + threadIdx.x;
    if (k >= KCODE) return;
    const float* e = emb + (size_t)k * DIM;
    float s = 0.f;
    for (int d = 0; d < DIM; d++) {
        float v = e[d];
        s = __fadd_rn(s, __fmul_rn(v, v));
    }
    g_enorm[k] = s;
}

// ---------------------------------------------------------------- e -> (e*1024) fp16 hi/lo
__global__ void prep_kernel(const float* __restrict__ emb) {
    int idx = blockIdx.x * blockDim.x + threadIdx.x;
    if (idx >= KCODE * DIM) return;
    int k = idx >> 7, d = idx & 127;
    float v = emb[idx] * 1024.0f;                 // exact scaling
    __half h = __float2half_rn(v);
    __half l = __float2half_rn(v - __half2float(h));
    g_ehi[k * EPAD + d] = h;
    g_elo[k * EPAD + d] = l;
}

// ---------------------------------------------------------------- argmin via mma.sync
// 128 threads = 4 warps; warp w owns rows blockIdx.x*64 + w*16 .. +15.
// dot = zhi*ehi + zhi*elo + zlo*ehi (fp32 accum); dropped term ~2.6e-9.
extern __shared__ char asm_smem[];

__global__ __launch_bounds__(128, 2) void argmin_mma(const float* __restrict__ z) {
    char* smem = asm_smem;
    const uint32_t sbase = smem_u32(smem);
    const int tid = threadIdx.x, wid = tid >> 5, lane = tid & 31;
    const int g = lane >> 2, cc = lane & 3;
    const int row0w = blockIdx.x * 64 + wid * 16;
    const int rA = row0w + g, rB = rA + 8;

    // zn for the warp's 16 rows (lanes 0-15, sequential reference order)
    float znl = 0.f;
    if (lane < 16) {
        const float* zr = z + (size_t)(row0w + lane) * DIM;
        for (int d = 0; d < DIM; d++)
            znl = __fadd_rn(znl, __fmul_rn(zr[d], zr[d]));
    }
    const float znA = __shfl_sync(0xffffffffu, znl, g);
    const float znB = __shfl_sync(0xffffffffu, znl, g + 8);

    // Resident A fragments (hi+lo) for 8 k-steps.
    uint32_t ahi[32], alo[32];
    #pragma unroll
    for (int ks = 0; ks < 8; ks++) {
        float2 a0 = *(const float2*)(z + (size_t)rA * DIM + ks * 16 + 2 * cc);
        float2 a1 = *(const float2*)(z + (size_t)rB * DIM + ks * 16 + 2 * cc);
        float2 a2 = *(const float2*)(z + (size_t)rA * DIM + ks * 16 + 2 * cc + 8);
        float2 a3 = *(const float2*)(z + (size_t)rB * DIM + ks * 16 + 2 * cc + 8);
        split2(a0, ahi[ks * 4 + 0], alo[ks * 4 + 0]);
        split2(a1, ahi[ks * 4 + 1], alo[ks * 4 + 1]);
        split2(a2, ahi[ks * 4 + 2], alo[ks * 4 + 2]);
        split2(a3, ahi[ks * 4 + 3], alo[ks * 4 + 3]);
    }

    // Preload chunk 0.
    {
        uint32_t dst = sbase;
        const char* hs = (const char*)(g_ehi);
        const char* ls = (const char*)(g_elo);
        for (int i = tid; i < CHUNK_U4; i += 128) {
            cpasync16(dst + i * 16,           hs + i * 16);
            cpasync16(dst + CHUNK_B + i * 16, ls + i * 16);
        }
        CP_COMMIT(); CP_WAIT0();
    }
    __syncthreads();

    float minvA = FLT_MAX, minvB = FLT_MAX;
    int   miniA = 0, miniB = 0;

    for (int c = 0; c < NCHUNK; c++) {
        // prefetch next chunk into the other buffer
        if (c + 1 < NCHUNK) {
            uint32_t dst = sbase + ((c + 1) & 1) * BUF_B;
            const char* hs = (const char*)(g_ehi + (size_t)(c + 1) * BN * EPAD);
            const char* ls = (const char*)(g_elo + (size_t)(c + 1) * BN * EPAD);
            for (int i = tid; i < CHUNK_U4; i += 128) {
                cpasync16(dst + i * 16,           hs + i * 16);
                cpasync16(dst + CHUNK_B + i * 16, ls + i * 16);
            }
            CP_COMMIT();
        }

        const char* bh = smem + (c & 1) * BUF_B;
        const char* bl = bh + CHUNK_B;

        float acc[8][4];
        #pragma unroll
        for (int nt = 0; nt < 8; nt++)
            #pragma unroll
            for (int q = 0; q < 4; q++) acc[nt][q] = 0.f;

        #pragma unroll
        for (int ks = 0; ks < 8; ks++) {
            #pragma unroll
            for (int nt = 0; nt < 8; nt++) {
                uint32_t off = (uint32_t)((nt * 8 + g) * (EPAD * 2) + ks * 32 + cc * 4);
                uint32_t bh0 = *(const uint32_t*)(bh + off);
                uint32_t bh1 = *(const uint32_t*)(bh + off + 16);
                uint32_t bl0 = *(const uint32_t*)(bl + off);
                uint32_t bl1 = *(const uint32_t*)(bl + off + 16);
                mma16816(acc[nt], &ahi[ks * 4], bh0, bh1);   // hi*hi
                mma16816(acc[nt], &ahi[ks * 4], bl0, bl1);   // hi*lo
                mma16816(acc[nt], &alo[ks * 4], bh0, bh1);   // lo*hi
            }
        }

        // epilogue: q = (zn + en) + dot * (-2^-9)  [unscale 1/1024 and -2 folded, exact]
        const int cbase = c * BN;
        #pragma unroll
        for (int nt = 0; nt < 8; nt++) {
            int code0 = cbase + nt * 8 + 2 * cc;
            float2 en2 = *(const float2*)(g_enorm + code0);
            float q0 = __fadd_rn(__fadd_rn(znA, en2.x), acc[nt][0] * -0.001953125f);
            if (q0 < minvA) { minvA = q0; miniA = code0; }
            float q1 = __fadd_rn(__fadd_rn(znA, en2.y), acc[nt][1] * -0.001953125f);
            if (q1 < minvA) { minvA = q1; miniA = code0 + 1; }
            float q2 = __fadd_rn(__fadd_rn(znB, en2.x), acc[nt][2] * -0.001953125f);
            if (q2 < minvB) { minvB = q2; miniB = code0; }
            float q3 = __fadd_rn(__fadd_rn(znB, en2.y), acc[nt][3] * -0.001953125f);
            if (q3 < minvB) { minvB = q3; miniB = code0 + 1; }
        }

        if (c + 1 < NCHUNK) CP_WAIT0();
        __syncthreads();
    }

    // lexicographic (value, index) reduce across the 4 lanes sharing each row
    #pragma unroll
    for (int o = 1; o <= 2; o <<= 1) {
        float vA = __shfl_xor_sync(0xffffffffu, minvA, o);
        int   iA = __shfl_xor_sync(0xffffffffu, miniA, o);
        if (vA < minvA || (vA == minvA && iA < miniA)) { minvA = vA; miniA = iA; }
        float vB = __shfl_xor_sync(0xffffffffu, minvB, o);
        int   iB = __shfl_xor_sync(0xffffffffu, miniB, o);
        if (vB < minvB || (vB == minvB && iB < miniB)) { minvB = vB; miniB = iB; }
    }
    if (cc == 0) {
        g_idx[rA] = miniA;
        g_idx[rB] = miniB;
    }
}

// ---------------------------------------------------------------- gather + loss + hist
__global__ void quantize_kernel(const float* __restrict__ z,
                                const float* __restrict__ emb,
                                const unsigned char* __restrict__ mask,
                                float* __restrict__ out) {
    const int warp = threadIdx.x >> 5;
    const int lane = threadIdx.x & 31;
    const int row  = blockIdx.x * QBLK + warp;
    const int code = g_idx[row];

    const float4 zv = *(const float4*)(z   + (size_t)row  * DIM + lane * 4);
    const float4 ev = *(const float4*)(emb + (size_t)code * DIM + lane * 4);

    float dx = __fadd_rn(ev.x, -zv.x);
    float dy = __fadd_rn(ev.y, -zv.y);
    float dz = __fadd_rn(ev.z, -zv.z);
    float dw = __fadd_rn(ev.w, -zv.w);

    float4 o;
    o.x = __fadd_rn(zv.x, dx);
    o.y = __fadd_rn(zv.y, dy);
    o.z = __fadd_rn(zv.z, dz);
    o.w = __fadd_rn(zv.w, dw);
    *(float4*)(out + (size_t)row * DIM + lane * 4) = o;

    float ss = dx * dx + dy * dy + dz * dz + dw * dw;
    #pragma unroll
    for (int off = 16; off; off >>= 1) ss += __shfl_xor_sync(0xffffffffu, ss, off);

    __shared__ float sps[QBLK];
    if (lane == 0) {
        sps[warp] = ss;
        if (!mask[row]) atomicAdd(&g_counts[code], 1);
    }
    __syncthreads();
    if (threadIdx.x == 0) {
        double b = 0.0;
        #pragma unroll
        for (int w = 0; w < QBLK; w++) b += (double)sps[w];
        g_losspart[blockIdx.x] = b;
    }
}

// ---------------------------------------------------------------- scalars
__global__ void finalize_kernel(const unsigned char* __restrict__ mask,
                                float* __restrict__ out, long long out_size) {
    __shared__ double dred[1024];
    __shared__ int    ired[1024];
    __shared__ float  fred[1024];
    const int k = threadIdx.x;

    int vsum = 0;
    {
        const uchar4* m4 = (const uchar4*)mask;
        #pragma unroll
        for (int i = 0; i < (N_TOK / 4) / 1024; i++) {
            uchar4 m = m4[k + i * 1024];
            vsum += (m.x ? 0 : 1) + (m.y ? 0 : 1) + (m.z ? 0 : 1) + (m.w ? 0 : 1);
        }
    }
    double lsum = 0.0;
    #pragma unroll
    for (int i = 0; i < NQB / 1024; i++) lsum += g_losspart[k + i * 1024];
    dred[k] = lsum;
    ired[k] = vsum;
    __syncthreads();
    for (int s = 512; s > 0; s >>= 1) {
        if (k < s) { dred[k] += dred[k + s]; ired[k] += ired[k + s]; }
        __syncthreads();
    }
    const float valid = (float)ired[0];
    const double losssum = dred[0];

    float p = __fdiv_rn((float)g_counts[k], valid);
    fred[k] = __fmul_rn(p, logf(__fadd_rn(p, 1e-10f)));
    __syncthreads();
    for (int s = 512; s > 0; s >>= 1) {
        if (k < s) fred[k] += fred[k + s];
        __syncthreads();
    }
    if (k == 0 && out_size >= (long long)N_TOK * DIM + 2) {
        double mean = losssum / (double)((long long)N_TOK * DIM);
        float v = (float)mean;
        out[(long long)N_TOK * DIM]     = __fadd_rn(v, __fmul_rn(0.25f, v));
        out[(long long)N_TOK * DIM + 1] = expf(-fred[0]);
    }
}

// ---------------------------------------------------------------- launch
extern "C" void kernel_launch(void* const* d_in, const int* in_sizes, int n_in,
                              void* d_out, int out_size) {
    const float* z = nullptr;
    const float* emb = nullptr;
    const unsigned char* mask = nullptr;
    for (int i = 0; i < n_in; i++) {
        if      (in_sizes[i] == N_TOK * DIM) z    = (const float*)d_in[i];
        else if (in_sizes[i] == KCODE * DIM) emb  = (const float*)d_in[i];
        else if (in_sizes[i] == N_TOK)       mask = (const unsigned char*)d_in[i];
    }
    float* out = (float*)d_out;

    cudaFuncSetAttribute(argmin_mma, cudaFuncAttributeMaxDynamicSharedMemorySize, SMEM_B);

    init_kernel    <<<4, 256>>>();
    enorm_kernel   <<<4, 256>>>(emb);
    prep_kernel    <<<(KCODE * DIM) / 256, 256>>>(emb);
    argmin_mma     <<<N_TOK / 64, 128, SMEM_B>>>(z);
    quantize_kernel<<<NQB, QBLK * 32>>>(z, emb, mask, out);
    finalize_kernel<<<1, 1024>>>(mask, out, (long long)out_size);
}

// round 6
// speedup vs baseline: 5.1805x; 1.0184x over previous
#include <cuda_runtime.h>
#include <cuda_fp16.h>
#include <math.h>
#include <float.h>
#include <stdint.h>

// Problem constants: B=64, S=512, D=128, K=1024; N = B*S
#define N_TOK 32768
#define DIM   128
#define KCODE 1024
#define QBLK  8
#define NQB   (N_TOK / QBLK)

#define BN        64          // codes per chunk
#define NCHUNK    (KCODE / BN)
#define EPAD      136         // halves per padded e-row (272 B)
#define ROW_B     (EPAD * 2)  // 272
#define CHUNK_B   (BN * ROW_B)           // 17408 bytes per split per chunk
#define CHUNK_U4  (CHUNK_B / 16)         // 1088 uint4
#define BUF_B     (2 * CHUNK_B)          // hi+lo = 34816
#define SO_BUF    4096                   // buffers after enorm cache
#define SMEM_TOT  (SO_BUF + 2 * BUF_B)   // 73728

// Scratch (no allocations allowed)
__device__ int    g_idx[N_TOK];
__device__ float  g_enorm[KCODE];
__device__ int    g_counts[KCODE];
__device__ double g_losspart[NQB];
__device__ __half g_ehi[KCODE * EPAD];   // e * 1024, fp16 hi, padded rows
__device__ __half g_elo[KCODE * EPAD];   // residual lo

// ------------------------------------------------------------ helpers
__device__ __forceinline__ uint32_t smem_u32(const void* p) {
    uint32_t a;
    asm("{ .reg .u64 t; cvta.to.shared.u64 t, %1; cvt.u32.u64 %0, t; }" : "=r"(a) : "l"(p));
    return a;
}
__device__ __forceinline__ void cpasync16(uint32_t dst, const void* src) {
    asm volatile("{\n\t.reg .u64 gp;\n\tcvta.to.global.u64 gp, %1;\n\t"
                 "cp.async.cg.shared.global [%0], [gp], 16;\n\t}"
                 :: "r"(dst), "l"(src));
}
#define CP_COMMIT() asm volatile("cp.async.commit_group;" ::: "memory")
#define CP_WAIT0()  asm volatile("cp.async.wait_group 0;" ::: "memory")

__device__ __forceinline__ void ldmatrix_x4(uint32_t& r0, uint32_t& r1,
                                            uint32_t& r2, uint32_t& r3, uint32_t addr) {
    asm volatile("ldmatrix.sync.aligned.m8n8.x4.shared.b16 {%0,%1,%2,%3}, [%4];"
                 : "=r"(r0), "=r"(r1), "=r"(r2), "=r"(r3) : "r"(addr));
}

// m16n8k16 row.col f32.f16.f16.f32
__device__ __forceinline__ void mma16816(float* c, const uint32_t* a,
                                         uint32_t b0, uint32_t b1) {
    asm volatile("mma.sync.aligned.m16n8k16.row.col.f32.f16.f16.f32 "
                 "{%0,%1,%2,%3}, {%4,%5,%6,%7}, {%8,%9}, {%0,%1,%2,%3};"
                 : "+f"(c[0]), "+f"(c[1]), "+f"(c[2]), "+f"(c[3])
                 : "r"(a[0]), "r"(a[1]), "r"(a[2]), "r"(a[3]), "r"(b0), "r"(b1));
}
__device__ __forceinline__ void split2(float2 v, uint32_t& h, uint32_t& l) {
    __half hx = __float2half_rn(v.x), hy = __float2half_rn(v.y);
    __half lx = __float2half_rn(v.x - __half2float(hx));
    __half ly = __float2half_rn(v.y - __half2float(hy));
    h = ((uint32_t)__half_as_ushort(hy) << 16) | __half_as_ushort(hx);
    l = ((uint32_t)__half_as_ushort(ly) << 16) | __half_as_ushort(lx);
}

// ---------------------------------------------------------------- init
__global__ void init_kernel() {
    int i = blockIdx.x * blockDim.x + threadIdx.x;
    if (i < KCODE) g_counts[i] = 0;
}

// ---------------------------------------------------------------- ||e||^2 (reference order)
__global__ void enorm_kernel(const float* __restrict__ emb) {
    int k = blockIdx.x * blockDim.x + threadIdx.x;
    if (k >= KCODE) return;
    const float* e = emb + (size_t)k * DIM;
    float s = 0.f;
    for (int d = 0; d < DIM; d++) {
        float v = e[d];
        s = __fadd_rn(s, __fmul_rn(v, v));
    }
    g_enorm[k] = s;
}

// ---------------------------------------------------------------- e -> (e*1024) fp16 hi/lo
__global__ void prep_kernel(const float* __restrict__ emb) {
    int idx = blockIdx.x * blockDim.x + threadIdx.x;
    if (idx >= KCODE * DIM) return;
    int k = idx >> 7, d = idx & 127;
    float v = emb[idx] * 1024.0f;                 // exact scaling
    __half h = __float2half_rn(v);
    __half l = __float2half_rn(v - __half2float(h));
    g_ehi[k * EPAD + d] = h;
    g_elo[k * EPAD + d] = l;
}

// ---------------------------------------------------------------- argmin via mma.sync
// 128 threads = 4 warps; warp w owns rows blockIdx.x*64 + w*16 .. +15.
// dot = zhi*ehi + zhi*elo + zlo*ehi (fp32 accum).
extern __shared__ char asm_smem[];

__global__ __launch_bounds__(128, 3) void argmin_mma(const float* __restrict__ z) {
    char* smem = asm_smem;
    const uint32_t sbase = smem_u32(smem);
    float* s_en = (float*)smem;
    const int tid = threadIdx.x, wid = tid >> 5, lane = tid & 31;
    const int g = lane >> 2, cc = lane & 3;
    const int row0w = blockIdx.x * 64 + wid * 16;
    const int rA = row0w + g, rB = rA + 8;

    // ldmatrix per-lane row pointer offset: lanes 0-7 -> bh k0..7, 8-15 -> bh k8..15,
    // 16-23 -> bl k0..7, 24-31 -> bl k8..15 (matrix row = code n)
    const int sel = lane >> 3, r8 = lane & 7;
    const uint32_t laneoff = (uint32_t)((sel >> 1) * CHUNK_B + (sel & 1) * 16 + r8 * ROW_B);

    // enorm -> smem (once)
    for (int i = tid; i < KCODE; i += 128) s_en[i] = g_enorm[i];

    // zn for the warp's 16 rows (lanes 0-15, sequential reference order)
    float znl = 0.f;
    if (lane < 16) {
        const float* zr = z + (size_t)(row0w + lane) * DIM;
        for (int d = 0; d < DIM; d++)
            znl = __fadd_rn(znl, __fmul_rn(zr[d], zr[d]));
    }
    const float znA = __shfl_sync(0xffffffffu, znl, g);
    const float znB = __shfl_sync(0xffffffffu, znl, g + 8);

    // Resident A fragments (hi+lo) for 8 k-steps.
    uint32_t ahi[32], alo[32];
    #pragma unroll
    for (int ks = 0; ks < 8; ks++) {
        float2 a0 = *(const float2*)(z + (size_t)rA * DIM + ks * 16 + 2 * cc);
        float2 a1 = *(const float2*)(z + (size_t)rB * DIM + ks * 16 + 2 * cc);
        float2 a2 = *(const float2*)(z + (size_t)rA * DIM + ks * 16 + 2 * cc + 8);
        float2 a3 = *(const float2*)(z + (size_t)rB * DIM + ks * 16 + 2 * cc + 8);
        split2(a0, ahi[ks * 4 + 0], alo[ks * 4 + 0]);
        split2(a1, ahi[ks * 4 + 1], alo[ks * 4 + 1]);
        split2(a2, ahi[ks * 4 + 2], alo[ks * 4 + 2]);
        split2(a3, ahi[ks * 4 + 3], alo[ks * 4 + 3]);
    }

    // Preload chunk 0.
    {
        uint32_t dst = sbase + SO_BUF;
        const char* hs = (const char*)(g_ehi);
        const char* ls = (const char*)(g_elo);
        for (int i = tid; i < CHUNK_U4; i += 128) {
            cpasync16(dst + i * 16,           hs + i * 16);
            cpasync16(dst + CHUNK_B + i * 16, ls + i * 16);
        }
        CP_COMMIT(); CP_WAIT0();
    }
    __syncthreads();

    float minvA = FLT_MAX, minvB = FLT_MAX;
    int   miniA = 0, miniB = 0;

    for (int c = 0; c < NCHUNK; c++) {
        // prefetch next chunk into the other buffer
        if (c + 1 < NCHUNK) {
            uint32_t dst = sbase + SO_BUF + ((c + 1) & 1) * BUF_B;
            const char* hs = (const char*)(g_ehi + (size_t)(c + 1) * BN * EPAD);
            const char* ls = (const char*)(g_elo + (size_t)(c + 1) * BN * EPAD);
            for (int i = tid; i < CHUNK_U4; i += 128) {
                cpasync16(dst + i * 16,           hs + i * 16);
                cpasync16(dst + CHUNK_B + i * 16, ls + i * 16);
            }
            CP_COMMIT();
        }

        const uint32_t bbase = sbase + SO_BUF + (c & 1) * BUF_B + laneoff;
        const int cbase = c * BN;

        #pragma unroll
        for (int g2 = 0; g2 < 2; g2++) {
            float acc[4][4];
            #pragma unroll
            for (int t = 0; t < 4; t++)
                #pragma unroll
                for (int q = 0; q < 4; q++) acc[t][q] = 0.f;

            #pragma unroll
            for (int ks = 0; ks < 8; ks++) {
                #pragma unroll
                for (int ntl = 0; ntl < 4; ntl++) {
                    const int nt = g2 * 4 + ntl;
                    uint32_t b0, b1, b2, b3;
                    ldmatrix_x4(b0, b1, b2, b3, bbase + nt * (8 * ROW_B) + ks * 32);
                    mma16816(acc[ntl], &ahi[ks * 4], b0, b1);   // hi*hi
                    mma16816(acc[ntl], &ahi[ks * 4], b2, b3);   // hi*lo
                    mma16816(acc[ntl], &alo[ks * 4], b0, b1);   // lo*hi
                }
            }

            // q = (zn + en) + dot * (-2^-9) [mul exact], identical rounding to before
            float qA[8], qB[8];
            #pragma unroll
            for (int ntl = 0; ntl < 4; ntl++) {
                int code0 = cbase + (g2 * 4 + ntl) * 8 + 2 * cc;
                float2 en2 = *(const float2*)(s_en + code0);
                qA[2*ntl]   = __fadd_rn(__fadd_rn(znA, en2.x), acc[ntl][0] * -0.001953125f);
                qA[2*ntl+1] = __fadd_rn(__fadd_rn(znA, en2.y), acc[ntl][1] * -0.001953125f);
                qB[2*ntl]   = __fadd_rn(__fadd_rn(znB, en2.x), acc[ntl][2] * -0.001953125f);
                qB[2*ntl+1] = __fadd_rn(__fadd_rn(znB, en2.y), acc[ntl][3] * -0.001953125f);
            }
            // min tree (FMNMX), then rare first-index rescan
            float cmA = fminf(fminf(fminf(qA[0], qA[1]), fminf(qA[2], qA[3])),
                              fminf(fminf(qA[4], qA[5]), fminf(qA[6], qA[7])));
            if (cmA < minvA) {
                minvA = cmA;
                #pragma unroll
                for (int t = 7; t >= 0; t--)
                    if (qA[t] == cmA)
                        miniA = cbase + g2 * 32 + (t >> 1) * 8 + 2 * cc + (t & 1);
            }
            float cmB = fminf(fminf(fminf(qB[0], qB[1]), fminf(qB[2], qB[3])),
                              fminf(fminf(qB[4], qB[5]), fminf(qB[6], qB[7])));
            if (cmB < minvB) {
                minvB = cmB;
                #pragma unroll
                for (int t = 7; t >= 0; t--)
                    if (qB[t] == cmB)
                        miniB = cbase + g2 * 32 + (t >> 1) * 8 + 2 * cc + (t & 1);
            }
        }

        if (c + 1 < NCHUNK) CP_WAIT0();
        __syncthreads();
    }

    // lexicographic (value, index) reduce across the 4 lanes sharing each row
    #pragma unroll
    for (int o = 1; o <= 2; o <<= 1) {
        float vA = __shfl_xor_sync(0xffffffffu, minvA, o);
        int   iA = __shfl_xor_sync(0xffffffffu, miniA, o);
        if (vA < minvA || (vA == minvA && iA < miniA)) { minvA = vA; miniA = iA; }
        float vB = __shfl_xor_sync(0xffffffffu, minvB, o);
        int   iB = __shfl_xor_sync(0xffffffffu, miniB, o);
        if (vB < minvB || (vB == minvB && iB < miniB)) { minvB = vB; miniB = iB; }
    }
    if (cc == 0) {
        g_idx[rA] = miniA;
        g_idx[rB] = miniB;
    }
}

// ---------------------------------------------------------------- gather + loss + hist
__global__ void quantize_kernel(const float* __restrict__ z,
                                const float* __restrict__ emb,
                                const unsigned char* __restrict__ mask,
                                float* __restrict__ out) {
    const int warp = threadIdx.x >> 5;
    const int lane = threadIdx.x & 31;
    const int row  = blockIdx.x * QBLK + warp;
    const int code = g_idx[row];

    const float4 zv = *(const float4*)(z   + (size_t)row  * DIM + lane * 4);
    const float4 ev = *(const float4*)(emb + (size_t)code * DIM + lane * 4);

    float dx = __fadd_rn(ev.x, -zv.x);
    float dy = __fadd_rn(ev.y, -zv.y);
    float dz = __fadd_rn(ev.z, -zv.z);
    float dw = __fadd_rn(ev.w, -zv.w);

    float4 o;
    o.x = __fadd_rn(zv.x, dx);
    o.y = __fadd_rn(zv.y, dy);
    o.z = __fadd_rn(zv.z, dz);
    o.w = __fadd_rn(zv.w, dw);
    *(float4*)(out + (size_t)row * DIM + lane * 4) = o;

    float ss = dx * dx + dy * dy + dz * dz + dw * dw;
    #pragma unroll
    for (int off = 16; off; off >>= 1) ss += __shfl_xor_sync(0xffffffffu, ss, off);

    __shared__ float sps[QBLK];
    if (lane == 0) {
        sps[warp] = ss;
        if (!mask[row]) atomicAdd(&g_counts[code], 1);
    }
    __syncthreads();
    if (threadIdx.x == 0) {
        double b = 0.0;
        #pragma unroll
        for (int w = 0; w < QBLK; w++) b += (double)sps[w];
        g_losspart[blockIdx.x] = b;
    }
}

// ---------------------------------------------------------------- scalars
__global__ void finalize_kernel(const unsigned char* __restrict__ mask,
                                float* __restrict__ out, long long out_size) {
    __shared__ double dred[1024];
    __shared__ int    ired[1024];
    __shared__ float  fred[1024];
    const int k = threadIdx.x;

    int vsum = 0;
    {
        const uchar4* m4 = (const uchar4*)mask;
        #pragma unroll
        for (int i = 0; i < (N_TOK / 4) / 1024; i++) {
            uchar4 m = m4[k + i * 1024];
            vsum += (m.x ? 0 : 1) + (m.y ? 0 : 1) + (m.z ? 0 : 1) + (m.w ? 0 : 1);
        }
    }
    double lsum = 0.0;
    #pragma unroll
    for (int i = 0; i < NQB / 1024; i++) lsum += g_losspart[k + i * 1024];
    dred[k] = lsum;
    ired[k] = vsum;
    __syncthreads();
    for (int s = 512; s > 0; s >>= 1) {
        if (k < s) { dred[k] += dred[k + s]; ired[k] += ired[k + s]; }
        __syncthreads();
    }
    const float valid = (float)ired[0];
    const double losssum = dred[0];

    float p = __fdiv_rn((float)g_counts[k], valid);
    fred[k] = __fmul_rn(p, logf(__fadd_rn(p, 1e-10f)));
    __syncthreads();
    for (int s = 512; s > 0; s >>= 1) {
        if (k < s) fred[k] += fred[k + s];
        __syncthreads();
    }
    if (k == 0 && out_size >= (long long)N_TOK * DIM + 2) {
        double mean = losssum / (double)((long long)N_TOK * DIM);
        float v = (float)mean;
        out[(long long)N_TOK * DIM]     = __fadd_rn(v, __fmul_rn(0.25f, v));
        out[(long long)N_TOK * DIM + 1] = expf(-fred[0]);
    }
}

// ---------------------------------------------------------------- launch
extern "C" void kernel_launch(void* const* d_in, const int* in_sizes, int n_in,
                              void* d_out, int out_size) {
    const float* z = nullptr;
    const float* emb = nullptr;
    const unsigned char* mask = nullptr;
    for (int i = 0; i < n_in; i++) {
        if      (in_sizes[i] == N_TOK * DIM) z    = (const float*)d_in[i];
        else if (in_sizes[i] == KCODE * DIM) emb  = (const float*)d_in[i];
        else if (in_sizes[i] == N_TOK)       mask = (const unsigned char*)d_in[i];
    }
    float* out = (float*)d_out;

    cudaFuncSetAttribute(argmin_mma, cudaFuncAttributeMaxDynamicSharedMemorySize, SMEM_TOT);

    init_kernel    <<<4, 256>>>();
    enorm_kernel   <<<4, 256>>>(emb);
    prep_kernel    <<<(KCODE * DIM) / 256, 256>>>(emb);
    argmin_mma     <<<N_TOK / 64, 128, SMEM_TOT>>>(z);
    quantize_kernel<<<NQB, QBLK * 32>>>(z, emb, mask, out);
    finalize_kernel<<<1, 1024>>>(mask, out, (long long)out_size);
}